// round 12
// baseline (speedup 1.0000x reference)
#include <cuda_runtime.h>
#include <math.h>

// NoisyTopKRouter eval-mode:
//   inputs:  x [4,8192,2048] f32, W_gate [2048,8] f32, W_noise (UNUSED), top_k=2
//   outputs (f32 in d_out): dispatch_weights [N,2], top_k_idx [N,2], aux scalar
//
// Lane-owns-row design: warp = 16 rows x 1024 cols. x is staged through a
// per-warp double-buffered smem tile stored TRANSPOSED with an XOR swizzle
// (conflict-free scattered writes AND strided reads). Each lane accumulates
// all 8 experts of its own row -> no butterflies. Weight loads are
// warp-(semi)uniform -> 2 wavefronts instead of 4. No block sync in the loop.

#define D         2048
#define NEXP      8
#define ROWS_W    16              // rows per warp
#define WPB       8               // warps per block
#define ROWS_B    64              // 4 rowgroups x 16
#define SCOLS     64              // columns per stage
#define STEPS     16              // float4 steps per stage
#define NSTG      2               // double buffer
#define NSTAGES   16              // 1024 cols / 64 per warp
#define STAGE_F4  (STEPS * ROWS_W)   // 256 float4 = 4 KB

__device__ float      g_load[NEXP];
__device__ float      g_imp[NEXP];
__device__ unsigned   g_ctr;
// Weight pairs: g_Wp[c*4+p] = (W[c][2p], W[c][2p+1]) packed f32x2. 64 KB.
__device__ unsigned long long g_Wp[D * 4];

__device__ __forceinline__ unsigned long long pack2(float x, float y) {
    unsigned long long r;
    asm("mov.b64 %0, {%1, %2};" : "=l"(r) : "f"(x), "f"(y));
    return r;
}
__device__ __forceinline__ void unpack2(unsigned long long v, float& x, float& y) {
    asm("mov.b64 {%0, %1}, %2;" : "=f"(x), "=f"(y) : "l"(v));
}
__device__ __forceinline__ void ffma2(unsigned long long& d,
                                      unsigned long long a, unsigned long long b) {
    asm("fma.rn.f32x2 %0, %1, %2, %0;" : "+l"(d) : "l"(a), "l"(b));
}
__device__ __forceinline__ unsigned long long add2(unsigned long long a,
                                                   unsigned long long b) {
    unsigned long long r;
    asm("add.rn.f32x2 %0, %1, %2;" : "=l"(r) : "l"(a), "l"(b));
    return r;
}
__device__ __forceinline__ void cp16(void* smem_dst, const void* gsrc) {
    unsigned s = (unsigned)__cvta_generic_to_shared(smem_dst);
    asm volatile("cp.async.cg.shared.global [%0], [%1], 16;"
                 :: "r"(s), "l"(gsrc) : "memory");
}
#define CP_COMMIT()  asm volatile("cp.async.commit_group;" ::: "memory")
#define CP_WAIT1()   asm volatile("cp.async.wait_group 1;" ::: "memory")

// Build packed weight pairs + zero accumulators.
__global__ void prep_kernel(const float* __restrict__ Wg) {
    const int c = blockIdx.x * 128 + threadIdx.x;      // column 0..2047
#pragma unroll
    for (int p = 0; p < 4; p++)
        g_Wp[c * 4 + p] = pack2(Wg[c * 8 + 2 * p], Wg[c * 8 + 2 * p + 1]);
    if (blockIdx.x == 0) {
        if (threadIdx.x < NEXP) { g_load[threadIdx.x] = 0.f; g_imp[threadIdx.x] = 0.f; }
        if (threadIdx.x == NEXP) g_ctr = 0u;
    }
}

__global__ __launch_bounds__(256, 2)
void router_main(const float* __restrict__ x,
                 float* __restrict__ out_w, float* __restrict__ out_idx,
                 float* __restrict__ out_aux) {
    extern __shared__ __align__(16) float4 s_x[];  // [WPB][NSTG][STAGE_F4] = 64 KB
    __shared__ float s_part[WPB][ROWS_W][9];       // [warp][row][expert] padded
    __shared__ float s_load[NEXP];
    __shared__ float s_imp[NEXP];
    __shared__ unsigned s_ticket;

    const int tid  = threadIdx.x;
    const int warp = tid >> 5;
    const int lane = tid & 31;
    const int g    = warp & 3;        // rowgroup
    const int h    = warp >> 2;       // column half
    const int rloc = lane & 15;       // this lane's local row
    const int sh   = lane >> 4;       // step-half (0/1)

    if (tid < NEXP) { s_load[tid] = 0.f; s_imp[tid] = 0.f; }
    __syncthreads();

    const int row0    = blockIdx.x * ROWS_B;
    const int rowbase = row0 + g * ROWS_W;
    const int colbase = h * 1024;
    const float* gx   = x + (size_t)rowbase * D + colbase;
    float4* sw = s_x + (size_t)(warp * NSTG) * STAGE_F4;

    // Stage writer: instr j covers rows {2j, 2j+1} x 64 cols; lane = step.
    // Element (row r, step s) lives at slot s*16 + (r ^ (s & 7))  -> 4-wf.
    const int wr = (lane >> 4);               // row offset within pair
    const int ws = lane & 15;                 // step for writes
    auto issue_stage = [&](int t) {
        float4* sb = sw + (t & 1) * STAGE_F4;
        const float* src0 = gx + t * SCOLS + ws * 4;
#pragma unroll
        for (int j = 0; j < 8; j++) {
            const int r = 2 * j + wr;
            cp16(sb + ws * 16 + (r ^ (ws & 7)), src0 + (size_t)r * D);
        }
        CP_COMMIT();
    };

    issue_stage(0);
    issue_stage(1);

    const unsigned long long* wp = g_Wp + (size_t)colbase * 4;
    unsigned long long acc[4] = {0ull, 0ull, 0ull, 0ull};

#pragma unroll 1
    for (int t = 0; t < NSTAGES; t++) {
        CP_WAIT1();                                 // stage t landed
        __syncwarp();
        const float4* sb = sw + (t & 1) * STAGE_F4;

#pragma unroll
        for (int d = 0; d < 8; d++) {
            const int s = 2 * d + sh;               // this lane's step
            float4 xv = sb[s * 16 + (rloc ^ (s & 7))];

            // Weights for this lane's 4 columns (semi-uniform: 2 addrs/warp).
            const unsigned long long* wq = wp + (size_t)(t * SCOLS + s * 4) * 4;
            unsigned long long q0 = __ldg(wq + 0),  q1 = __ldg(wq + 1);
            unsigned long long q2 = __ldg(wq + 2),  q3 = __ldg(wq + 3);
            unsigned long long q4 = __ldg(wq + 4),  q5 = __ldg(wq + 5);
            unsigned long long q6 = __ldg(wq + 6),  q7 = __ldg(wq + 7);
            unsigned long long q8 = __ldg(wq + 8),  q9 = __ldg(wq + 9);
            unsigned long long qa = __ldg(wq + 10), qb = __ldg(wq + 11);
            unsigned long long qc = __ldg(wq + 12), qd = __ldg(wq + 13);
            unsigned long long qe = __ldg(wq + 14), qf = __ldg(wq + 15);

            unsigned long long xb0 = pack2(xv.x, xv.x);
            unsigned long long xb1 = pack2(xv.y, xv.y);
            unsigned long long xb2 = pack2(xv.z, xv.z);
            unsigned long long xb3 = pack2(xv.w, xv.w);

            ffma2(acc[0], xb0, q0); ffma2(acc[1], xb0, q1);
            ffma2(acc[2], xb0, q2); ffma2(acc[3], xb0, q3);
            ffma2(acc[0], xb1, q4); ffma2(acc[1], xb1, q5);
            ffma2(acc[2], xb1, q6); ffma2(acc[3], xb1, q7);
            ffma2(acc[0], xb2, q8); ffma2(acc[1], xb2, q9);
            ffma2(acc[2], xb2, qa); ffma2(acc[3], xb2, qb);
            ffma2(acc[0], xb3, qc); ffma2(acc[1], xb3, qd);
            ffma2(acc[2], xb3, qe); ffma2(acc[3], xb3, qf);
        }

        __syncwarp();
        if (t + 2 < NSTAGES) issue_stage(t + 2);
        else CP_COMMIT();                           // keep group count aligned
    }

    // Combine the two step-halves (lane l and l+16 hold the same row).
#pragma unroll
    for (int p = 0; p < 4; p++)
        acc[p] = add2(acc[p], __shfl_xor_sync(0xffffffffu, acc[p], 16));

    if (lane < ROWS_W) {
#pragma unroll
        for (int p = 0; p < 4; p++) {
            float lo, hi;
            unpack2(acc[p], lo, hi);
            s_part[warp][lane][2 * p]     = lo;
            s_part[warp][lane][2 * p + 1] = hi;
        }
    }
    __syncthreads();

    // ---- epilogue: one thread per row (threads 0..63) ----
    if (tid < ROWS_B) {
        const int rg = tid >> 4, rl = tid & 15;
        const int row = row0 + tid;
        float hv[NEXP];
#pragma unroll
        for (int e = 0; e < NEXP; e++)
            hv[e] = s_part[rg][rl][e] + s_part[rg + 4][rl][e];

        // top-2 (lowest index wins ties, matching jax.lax.top_k)
        int e0 = 0; float v0 = hv[0];
#pragma unroll
        for (int e = 1; e < NEXP; e++)
            if (hv[e] > v0) { v0 = hv[e]; e0 = e; }
        int e1 = -1; float v1 = -3.4e38f;
#pragma unroll
        for (int e = 0; e < NEXP; e++)
            if (e != e0 && hv[e] > v1) { v1 = hv[e]; e1 = e; }

        float w0 = 1.f / (1.f + expf(v1 - v0));
        float w1 = 1.f - w0;

        float p[NEXP]; float Z = 0.f;
#pragma unroll
        for (int e = 0; e < NEXP; e++) { p[e] = expf(hv[e] - v0); Z += p[e]; }
        float invZ = 1.f / Z;
#pragma unroll
        for (int e = 0; e < NEXP; e++) atomicAdd(&s_imp[e], p[e] * invZ);
        atomicAdd(&s_load[e0], 1.f);
        atomicAdd(&s_load[e1], 1.f);

        out_w[row * 2]       = w0;
        out_w[row * 2 + 1]   = w1;
        out_idx[row * 2]     = (float)e0;
        out_idx[row * 2 + 1] = (float)e1;
    }

    __syncthreads();
    if (tid < NEXP) {
        atomicAdd(&g_load[tid], s_load[tid]);
        atomicAdd(&g_imp[tid],  s_imp[tid]);
        __threadfence();
    }
    __syncthreads();
    if (tid == 0) s_ticket = atomicAdd(&g_ctr, 1u);
    __syncthreads();

    // Last block computes the auxiliary loss.
    if (s_ticket == gridDim.x - 1 && tid == 0) {
        volatile float* vl_ = g_load;
        volatile float* vi_ = g_imp;
        float l[NEXP], im[NEXP];
        float ml = 0.f, mi = 0.f;
#pragma unroll
        for (int e = 0; e < NEXP; e++) {
            l[e] = vl_[e]; im[e] = vi_[e];
            ml += l[e];    mi += im[e];
        }
        ml *= (1.f / NEXP);
        mi *= (1.f / NEXP);
        float vl = 0.f, vi = 0.f;
#pragma unroll
        for (int e = 0; e < NEXP; e++) {
            float dl = l[e]  - ml; vl += dl * dl;
            float di = im[e] - mi; vi += di * di;
        }
        vl *= (1.f / (NEXP - 1));   // ddof = 1
        vi *= (1.f / (NEXP - 1));
        float cv = sqrtf(vl) / (ml + 1e-6f) + sqrtf(vi) / (mi + 1e-6f);
        *out_aux = cv * 0.01f;
    }
}

extern "C" void kernel_launch(void* const* d_in, const int* in_sizes, int n_in,
                              void* d_out, int out_size) {
    const float* x  = (const float*)d_in[0];   // [4,8192,2048]
    const float* Wg = (const float*)d_in[1];   // [2048,8]
    // d_in[2] = W_noise (unused in eval), d_in[3] = top_k (=2)

    const int N = in_sizes[0] / D;             // 32768 rows

    float* out     = (float*)d_out;
    float* out_w   = out;                      // [N,2]
    float* out_idx = out + (size_t)N * 2;      // [N,2]
    float* out_aux = out + (size_t)N * 4;      // scalar

    const int dsmem = WPB * NSTG * STAGE_F4 * (int)sizeof(float4);  // 64 KB
    static int attr_set = -1;
    if (attr_set < 0) {
        cudaFuncSetAttribute(router_main,
                             cudaFuncAttributeMaxDynamicSharedMemorySize, dsmem);
        attr_set = 1;
    }

    prep_kernel<<<16, 128>>>(Wg);
    router_main<<<N / ROWS_B, 256, dsmem>>>(x, out_w, out_idx, out_aux);
}

// round 13
// speedup vs baseline: 1.3524x; 1.3524x over previous
#include <cuda_runtime.h>
#include <math.h>

// NoisyTopKRouter eval-mode:
//   inputs:  x [4,8192,2048] f32, W_gate [2048,8] f32, W_noise (UNUSED), top_k=2
//   outputs (f32 in d_out): dispatch_weights [N,2], top_k_idx [N,2], aux scalar
//
// Column-split design: warp w owns cols [256w,256w+256); its 64 weight values
// live in 32 ull REGISTERS (loaded once per block -> zero weight traffic in the
// stream loop). x is read with dense 512B/warp LDG.128 (optimal wavefronts),
// 2 rows per batch, depth-1 batch prefetch. Per-batch reduction folds BOTH rows
// into one shfl tree (48 SHFL.32 per 2KB). Partials combine in smem; epilogue
// does top-2 + softmax; last block computes the aux loss.

#define D       2048
#define D4      512         // D / 4
#define NEXP    8
#define RPB     32          // rows per block
#define WPB     8           // warps per block (256 threads)
#define NBATCH  16          // batches of 2 rows

__device__ float      g_load[NEXP];
__device__ float      g_imp[NEXP];
__device__ unsigned   g_ctr;
// Packed weight pairs: g_Wp[c*4+p] = (W[c][2p], W[c][2p+1]) as f32x2. 64 KB.
__device__ unsigned long long g_Wp[D * 4];

__device__ __forceinline__ unsigned long long pack2(float x, float y) {
    unsigned long long r;
    asm("mov.b64 %0, {%1, %2};" : "=l"(r) : "f"(x), "f"(y));
    return r;
}
__device__ __forceinline__ void unpack2(unsigned long long v, float& x, float& y) {
    asm("mov.b64 {%0, %1}, %2;" : "=f"(x), "=f"(y) : "l"(v));
}
__device__ __forceinline__ void ffma2(unsigned long long& d,
                                      unsigned long long a, unsigned long long b) {
    asm("fma.rn.f32x2 %0, %1, %2, %0;" : "+l"(d) : "l"(a), "l"(b));
}
__device__ __forceinline__ unsigned long long add2(unsigned long long a,
                                                   unsigned long long b) {
    unsigned long long r;
    asm("add.rn.f32x2 %0, %1, %2;" : "=l"(r) : "l"(a), "l"(b));
    return r;
}

// Build packed weight pairs + zero accumulators.
__global__ void prep_kernel(const float* __restrict__ Wg) {
    const int c = blockIdx.x * 128 + threadIdx.x;      // column 0..2047
#pragma unroll
    for (int p = 0; p < 4; p++)
        g_Wp[c * 4 + p] = pack2(Wg[c * 8 + 2 * p], Wg[c * 8 + 2 * p + 1]);
    if (blockIdx.x == 0) {
        if (threadIdx.x < NEXP) { g_load[threadIdx.x] = 0.f; g_imp[threadIdx.x] = 0.f; }
        if (threadIdx.x == NEXP) g_ctr = 0u;
    }
}

__global__ __launch_bounds__(256, 2)
void router_main(const float* __restrict__ x,
                 float* __restrict__ out_w, float* __restrict__ out_idx,
                 float* __restrict__ out_aux) {
    __shared__ float s_part[WPB][RPB][9];   // [warp][row][expert], padded
    __shared__ float s_load[NEXP];
    __shared__ float s_imp[NEXP];
    __shared__ unsigned s_ticket;

    const int tid  = threadIdx.x;
    const int warp = tid >> 5;
    const int lane = tid & 31;

    if (tid < NEXP) { s_load[tid] = 0.f; s_imp[tid] = 0.f; }
    __syncthreads();

    const int row0 = blockIdx.x * RPB;

    // ---- weights -> registers (once per block) ----
    // Lane owns cols {w*256 + 4*lane + j} (q=0) and {w*256 + 128 + 4*lane + j} (q=1).
    unsigned long long wreg[2][4][4];
#pragma unroll
    for (int q = 0; q < 2; q++)
#pragma unroll
        for (int j = 0; j < 4; j++) {
            const int c = warp * 256 + q * 128 + lane * 4 + j;
            const ulonglong2* wp2 = (const ulonglong2*)(g_Wp + c * 4);
            ulonglong2 v0 = __ldg(wp2);
            ulonglong2 v1 = __ldg(wp2 + 1);
            wreg[q][j][0] = v0.x; wreg[q][j][1] = v0.y;
            wreg[q][j][2] = v1.x; wreg[q][j][3] = v1.y;
        }

    // x pointers: lane reads float4 #lane (q=0) and #lane+32 (q=1) of its slice.
    const float4* xb = (const float4*)x + (size_t)row0 * D4 + warp * 64 + lane;

    // Prime prefetch for batch 0 (rows 0,1).
    float4 xc0[2], xc1[2];
    xc0[0] = __ldcs(xb);            xc1[0] = __ldcs(xb + 32);
    xc0[1] = __ldcs(xb + D4);       xc1[1] = __ldcs(xb + D4 + 32);

#pragma unroll 1
    for (int b = 0; b < NBATCH; b++) {
        // Prefetch batch b+1 (dense 512B/warp LDG.128 x4 — 16 lines in flight).
        float4 xn0[2], xn1[2];
        if (b + 1 < NBATCH) {
            const float4* nb = xb + (size_t)(2 * (b + 1)) * D4;
            xn0[0] = __ldcs(nb);           xn1[0] = __ldcs(nb + 32);
            xn0[1] = __ldcs(nb + D4);      xn1[1] = __ldcs(nb + D4 + 32);
        }

        unsigned long long acc[2][4] = {{0,0,0,0},{0,0,0,0}};
#pragma unroll
        for (int r = 0; r < 2; r++)
#pragma unroll
            for (int q = 0; q < 2; q++) {
                const float4 xv = q ? xc1[r] : xc0[r];
#pragma unroll
                for (int j = 0; j < 4; j++) {
                    float xc = (j == 0) ? xv.x : (j == 1) ? xv.y
                             : (j == 2) ? xv.z : xv.w;
                    unsigned long long xbv = pack2(xc, xc);
                    ffma2(acc[r][0], xbv, wreg[q][j][0]);
                    ffma2(acc[r][1], xbv, wreg[q][j][1]);
                    ffma2(acc[r][2], xbv, wreg[q][j][2]);
                    ffma2(acc[r][3], xbv, wreg[q][j][3]);
                }
            }

        // Folded reduction: merge both rows into one tree.
        // After step 1, lanes 0-15 carry row 2b, lanes 16-31 carry row 2b+1.
        unsigned long long m[4];
#pragma unroll
        for (int p = 0; p < 4; p++) {
            unsigned long long a  = acc[0][p], c2 = acc[1][p];
            unsigned long long ta = __shfl_xor_sync(0xffffffffu, a,  16);
            unsigned long long tc = __shfl_xor_sync(0xffffffffu, c2, 16);
            unsigned long long mm = (lane < 16) ? add2(a, ta) : add2(c2, tc);
#pragma unroll
            for (int off = 8; off > 0; off >>= 1)
                mm = add2(mm, __shfl_xor_sync(0xffffffffu, mm, off));
            m[p] = mm;
        }

        if (lane == 0 || lane == 16) {
            const int r = 2 * b + (lane >> 4);
#pragma unroll
            for (int p = 0; p < 4; p++) {
                float lo, hi;
                unpack2(m[p], lo, hi);
                s_part[warp][r][2 * p]     = lo;
                s_part[warp][r][2 * p + 1] = hi;
            }
        }

        xc0[0] = xn0[0]; xc1[0] = xn1[0];
        xc0[1] = xn0[1]; xc1[1] = xn1[1];
    }

    __syncthreads();

    // ---- epilogue: one thread per row (threads 0..31) ----
    if (tid < RPB) {
        const int r = tid, row = row0 + r;
        float h[NEXP];
#pragma unroll
        for (int e = 0; e < NEXP; e++) {
            float sum = 0.f;
#pragma unroll
            for (int w = 0; w < WPB; w++) sum += s_part[w][r][e];
            h[e] = sum;
        }

        // top-2 (lowest index wins ties, matching jax.lax.top_k)
        int e0 = 0; float v0 = h[0];
#pragma unroll
        for (int e = 1; e < NEXP; e++)
            if (h[e] > v0) { v0 = h[e]; e0 = e; }
        int e1 = -1; float v1 = -3.4e38f;
#pragma unroll
        for (int e = 0; e < NEXP; e++)
            if (e != e0 && h[e] > v1) { v1 = h[e]; e1 = e; }

        float w0 = 1.f / (1.f + expf(v1 - v0));
        float w1 = 1.f - w0;

        float p[NEXP]; float Z = 0.f;
#pragma unroll
        for (int e = 0; e < NEXP; e++) { p[e] = expf(h[e] - v0); Z += p[e]; }
        float invZ = 1.f / Z;
#pragma unroll
        for (int e = 0; e < NEXP; e++) atomicAdd(&s_imp[e], p[e] * invZ);
        atomicAdd(&s_load[e0], 1.f);
        atomicAdd(&s_load[e1], 1.f);

        out_w[row * 2]       = w0;
        out_w[row * 2 + 1]   = w1;
        out_idx[row * 2]     = (float)e0;
        out_idx[row * 2 + 1] = (float)e1;
    }

    __syncthreads();
    if (tid < NEXP) {
        atomicAdd(&g_load[tid], s_load[tid]);
        atomicAdd(&g_imp[tid],  s_imp[tid]);
        __threadfence();
    }
    __syncthreads();
    if (tid == 0) s_ticket = atomicAdd(&g_ctr, 1u);
    __syncthreads();

    // Last block computes the auxiliary loss.
    if (s_ticket == gridDim.x - 1 && tid == 0) {
        volatile float* vl_ = g_load;
        volatile float* vi_ = g_imp;
        float l[NEXP], im[NEXP];
        float ml = 0.f, mi = 0.f;
#pragma unroll
        for (int e = 0; e < NEXP; e++) {
            l[e] = vl_[e]; im[e] = vi_[e];
            ml += l[e];    mi += im[e];
        }
        ml *= (1.f / NEXP);
        mi *= (1.f / NEXP);
        float vl = 0.f, vi = 0.f;
#pragma unroll
        for (int e = 0; e < NEXP; e++) {
            float dl = l[e]  - ml; vl += dl * dl;
            float di = im[e] - mi; vi += di * di;
        }
        vl *= (1.f / (NEXP - 1));   // ddof = 1
        vi *= (1.f / (NEXP - 1));
        float cv = sqrtf(vl) / (ml + 1e-6f) + sqrtf(vi) / (mi + 1e-6f);
        *out_aux = cv * 0.01f;
    }
}

extern "C" void kernel_launch(void* const* d_in, const int* in_sizes, int n_in,
                              void* d_out, int out_size) {
    const float* x  = (const float*)d_in[0];   // [4,8192,2048]
    const float* Wg = (const float*)d_in[1];   // [2048,8]
    // d_in[2] = W_noise (unused in eval), d_in[3] = top_k (=2)

    const int N = in_sizes[0] / D;             // 32768 rows

    float* out     = (float*)d_out;
    float* out_w   = out;                      // [N,2]
    float* out_idx = out + (size_t)N * 2;      // [N,2]
    float* out_aux = out + (size_t)N * 4;      // scalar

    prep_kernel<<<16, 128>>>(Wg);
    router_main<<<N / RPB, 256>>>(x, out_w, out_idx, out_aux);
}

// round 14
// speedup vs baseline: 1.8347x; 1.3566x over previous
#include <cuda_runtime.h>
#include <math.h>

// NoisyTopKRouter eval-mode:
//   inputs:  x [4,8192,2048] f32, W_gate [2048,8] f32, W_noise (UNUSED), top_k=2
//   outputs (f32 in d_out): dispatch_weights [N,2], top_k_idx [N,2], aux scalar
//
// R6-derived row-split design (best so far), with weight traffic split across
// memory ports: the rearranged 64KB weight table is staged in SMEM once per
// block; in the stream loop 'wa' (experts 0..3) comes from SMEM (LDS) and 'wb'
// (experts 4..7) from L1 (__ldg) -> L1 carries only half the weight bytes plus
// x miss-fills; smem carries wa + x ring reads + cp.async fills (~126B/cyc).

#define D        2048
#define D4       512        // D / 4
#define NEXP     8
#define RPW      4          // rows per warp
#define WPB      8          // warps per block (256 threads)
#define RPB      (RPW*WPB)  // 32 rows per block
#define NSTG     2          // x ring slots per warp

#define W_F4     4096                   // 64KB of weights as float4
#define RING_F4  (WPB*NSTG*RPW*32)      // 2048 float4 = 32KB

__device__ float    g_load[NEXP];
__device__ float    g_imp[NEXP];
__device__ unsigned g_ctr;
// Rearranged W_gate: [(i*4+j)*2 + half][lane] 16B units; half0 = experts 0..3,
// half1 = experts 4..7, for column c = i*128 + lane*4 + j  (i = 0..15).
__device__ float4   g_Wre[W_F4];        // 64 KB

__device__ __forceinline__ unsigned long long pack2(float x, float y) {
    unsigned long long r;
    asm("mov.b64 %0, {%1, %2};" : "=l"(r) : "f"(x), "f"(y));
    return r;
}
__device__ __forceinline__ void unpack2(unsigned long long v, float& x, float& y) {
    asm("mov.b64 {%0, %1}, %2;" : "=f"(x), "=f"(y) : "l"(v));
}
__device__ __forceinline__ void ffma2(unsigned long long& d,
                                      unsigned long long a, unsigned long long b) {
    asm("fma.rn.f32x2 %0, %1, %2, %0;" : "+l"(d) : "l"(a), "l"(b));
}
__device__ __forceinline__ unsigned long long add2(unsigned long long a,
                                                   unsigned long long b) {
    unsigned long long r;
    asm("add.rn.f32x2 %0, %1, %2;" : "=l"(r) : "l"(a), "l"(b));
    return r;
}
__device__ __forceinline__ void cp16(void* smem_dst, const void* gsrc) {
    unsigned s = (unsigned)__cvta_generic_to_shared(smem_dst);
    asm volatile("cp.async.cg.shared.global [%0], [%1], 16;"
                 :: "r"(s), "l"(gsrc) : "memory");
}
#define CP_COMMIT()  asm volatile("cp.async.commit_group;" ::: "memory")
#define CP_WAIT1()   asm volatile("cp.async.wait_group 1;" ::: "memory")

// Rearrange W_gate into loop-order layout + zero the global accumulators.
__global__ void prep_kernel(const float* __restrict__ Wg) {
    const int c = blockIdx.x * 128 + threadIdx.x;           // column 0..2047
    const float4* Wg4 = (const float4*)Wg;
    float4 f0 = Wg4[c * 2];                                  // experts 0..3
    float4 f1 = Wg4[c * 2 + 1];                              // experts 4..7
    const int i = c >> 7, r = c & 127, lane = r >> 2, j = r & 3;
    const int base = ((i * 4 + j) * 2) * 32 + lane;
    g_Wre[base]      = f0;
    g_Wre[base + 32] = f1;
    if (blockIdx.x == 0) {
        if (threadIdx.x < NEXP) { g_load[threadIdx.x] = 0.f; g_imp[threadIdx.x] = 0.f; }
        if (threadIdx.x == NEXP) g_ctr = 0u;
    }
}

__global__ __launch_bounds__(256, 2)
void router_main(const float* __restrict__ x,
                 float* __restrict__ out_w, float* __restrict__ out_idx,
                 float* __restrict__ out_aux) {
    extern __shared__ __align__(16) float4 smem_dyn[];
    float4* s_w = smem_dyn;                 // 64 KB weight table
    float4* s_r = smem_dyn + W_F4;          // 32 KB x ring: [warp][slot][row][lane]

    __shared__ float s_load[NEXP];
    __shared__ float s_imp[NEXP];
    __shared__ unsigned s_ticket;

    const int tid  = threadIdx.x;
    const int warp = tid >> 5;
    const int lane = tid & 31;

    if (tid < NEXP) { s_load[tid] = 0.f; s_imp[tid] = 0.f; }

    const int r0 = (blockIdx.x * WPB + warp) * RPW;          // first row for this warp
    const float4* gsrc = (const float4*)x + (size_t)r0 * D4 + lane;
    float4* ring = s_r + (warp * NSTG) * (RPW * 32);

    // G0: stage the 64KB weight table into smem (coalesced 16B copies).
#pragma unroll
    for (int k = 0; k < W_F4 / 256; k++)
        cp16(&s_w[k * 256 + tid], &g_Wre[k * 256 + tid]);
    CP_COMMIT();

    // G1, G2: x stages 0 and 1 (lane-private 16B copies).
#pragma unroll
    for (int st = 0; st < 2; st++) {
#pragma unroll
        for (int rr = 0; rr < RPW; rr++)
            cp16(&ring[st * (RPW * 32) + rr * 32 + lane], gsrc + rr * D4 + st * 32);
        CP_COMMIT();
    }

    CP_WAIT1();            // G0 (weights) + G1 (stage 0) landed
    __syncthreads();       // weights visible block-wide

    const ulonglong2* swq = (const ulonglong2*)s_w;          // smem weights
    const ulonglong2* gwq = (const ulonglong2*)g_Wre;        // L1 weights

    unsigned long long acc[RPW][4];
#pragma unroll
    for (int rr = 0; rr < RPW; rr++)
#pragma unroll
        for (int p = 0; p < 4; p++) acc[rr][p] = 0ull;

#pragma unroll 1
    for (int i = 0; i < 16; i++) {                           // 16 groups of 128 cols
        const int sl = i & 1;
        float4 xv[RPW];
#pragma unroll
        for (int rr = 0; rr < RPW; rr++)
            xv[rr] = ring[sl * (RPW * 32) + rr * 32 + lane];

#pragma unroll
        for (int j = 0; j < 4; j++) {
            // wa from SMEM port, wb from L1 port (balanced traffic)
            ulonglong2 wa = swq[((i * 4 + j) * 2 + 0) * 32 + lane];       // e0..3
            ulonglong2 wb = __ldg(&gwq[((i * 4 + j) * 2 + 1) * 32 + lane]); // e4..7
#pragma unroll
            for (int rr = 0; rr < RPW; rr++) {
                float xc = (j == 0) ? xv[rr].x : (j == 1) ? xv[rr].y
                         : (j == 2) ? xv[rr].z : xv[rr].w;
                unsigned long long xb = pack2(xc, xc);
                ffma2(acc[rr][0], xb, wa.x);
                ffma2(acc[rr][1], xb, wa.y);
                ffma2(acc[rr][2], xb, wb.x);
                ffma2(acc[rr][3], xb, wb.y);
            }
        }

        // Refill this slot with stage i+2 (lane-private; reads above already issued).
        if (i + 2 < 16) {
#pragma unroll
            for (int rr = 0; rr < RPW; rr++)
                cp16(&ring[sl * (RPW * 32) + rr * 32 + lane],
                     gsrc + rr * D4 + (i + 2) * 32);
        }
        CP_COMMIT();       // exactly one group per iteration (possibly empty)
        CP_WAIT1();        // stage i+1 landed; only the refill stays pending
    }

    // Cross-lane reduction ONCE (16 independent 5-step chains).
#pragma unroll
    for (int rr = 0; rr < RPW; rr++)
#pragma unroll
        for (int p = 0; p < 4; p++) {
#pragma unroll
            for (int off = 16; off > 0; off >>= 1)
                acc[rr][p] = add2(acc[rr][p],
                                  __shfl_xor_sync(0xffffffffu, acc[rr][p], off));
        }

    // Lane rr owns row r0+rr for the epilogue.
    unsigned long long mine[4];
#pragma unroll
    for (int rr = 0; rr < RPW; rr++)
        if (lane == rr) {
            mine[0] = acc[rr][0]; mine[1] = acc[rr][1];
            mine[2] = acc[rr][2]; mine[3] = acc[rr][3];
        }

    if (lane < RPW) {
        float h[NEXP];
        unpack2(mine[0], h[0], h[1]);
        unpack2(mine[1], h[2], h[3]);
        unpack2(mine[2], h[4], h[5]);
        unpack2(mine[3], h[6], h[7]);

        const int row = r0 + lane;

        // top-2 (lowest index wins ties, matching jax.lax.top_k)
        int e0 = 0; float v0 = h[0];
#pragma unroll
        for (int e = 1; e < NEXP; e++)
            if (h[e] > v0) { v0 = h[e]; e0 = e; }
        int e1 = -1; float v1 = -3.4e38f;
#pragma unroll
        for (int e = 0; e < NEXP; e++)
            if (e != e0 && h[e] > v1) { v1 = h[e]; e1 = e; }

        float w0 = 1.f / (1.f + expf(v1 - v0));
        float w1 = 1.f - w0;

        float p[NEXP]; float Z = 0.f;
#pragma unroll
        for (int e = 0; e < NEXP; e++) { p[e] = expf(h[e] - v0); Z += p[e]; }
        float invZ = 1.f / Z;
#pragma unroll
        for (int e = 0; e < NEXP; e++) atomicAdd(&s_imp[e], p[e] * invZ);
        atomicAdd(&s_load[e0], 1.f);
        atomicAdd(&s_load[e1], 1.f);

        out_w[row * 2]       = w0;
        out_w[row * 2 + 1]   = w1;
        out_idx[row * 2]     = (float)e0;
        out_idx[row * 2 + 1] = (float)e1;
    }

    __syncthreads();
    if (tid < NEXP) {
        atomicAdd(&g_load[tid], s_load[tid]);
        atomicAdd(&g_imp[tid],  s_imp[tid]);
        __threadfence();
    }
    __syncthreads();
    if (tid == 0) s_ticket = atomicAdd(&g_ctr, 1u);
    __syncthreads();

    // Last block computes the auxiliary loss.
    if (s_ticket == gridDim.x - 1 && tid == 0) {
        volatile float* vl_ = g_load;
        volatile float* vi_ = g_imp;
        float l[NEXP], im[NEXP];
        float ml = 0.f, mi = 0.f;
#pragma unroll
        for (int e = 0; e < NEXP; e++) {
            l[e] = vl_[e]; im[e] = vi_[e];
            ml += l[e];    mi += im[e];
        }
        ml *= (1.f / NEXP);
        mi *= (1.f / NEXP);
        float vl = 0.f, vi = 0.f;
#pragma unroll
        for (int e = 0; e < NEXP; e++) {
            float dl = l[e]  - ml; vl += dl * dl;
            float di = im[e] - mi; vi += di * di;
        }
        vl *= (1.f / (NEXP - 1));   // ddof = 1
        vi *= (1.f / (NEXP - 1));
        float cv = sqrtf(vl) / (ml + 1e-6f) + sqrtf(vi) / (mi + 1e-6f);
        *out_aux = cv * 0.01f;
    }
}

extern "C" void kernel_launch(void* const* d_in, const int* in_sizes, int n_in,
                              void* d_out, int out_size) {
    const float* x  = (const float*)d_in[0];   // [4,8192,2048]
    const float* Wg = (const float*)d_in[1];   // [2048,8]
    // d_in[2] = W_noise (unused in eval), d_in[3] = top_k (=2)

    const int N = in_sizes[0] / D;             // 32768 rows

    float* out     = (float*)d_out;
    float* out_w   = out;                      // [N,2]
    float* out_idx = out + (size_t)N * 2;      // [N,2]
    float* out_aux = out + (size_t)N * 4;      // scalar

    const int dsmem = (W_F4 + RING_F4) * (int)sizeof(float4);  // 96 KB
    static int attr_set = -1;
    if (attr_set < 0) {
        cudaFuncSetAttribute(router_main,
                             cudaFuncAttributeMaxDynamicSharedMemorySize, dsmem);
        attr_set = 1;
    }

    prep_kernel<<<16, 128>>>(Wg);
    router_main<<<N / RPB, 256, dsmem>>>(x, out_w, out_idx, out_aux);
}

// round 15
// speedup vs baseline: 1.9885x; 1.0838x over previous
#include <cuda_runtime.h>
#include <math.h>

// NoisyTopKRouter eval-mode:
//   inputs:  x [4,8192,2048] f32, W_gate [2048,8] f32, W_noise (UNUSED), top_k=2
//   outputs (f32, concatenated in d_out):
//     dispatch_weights [N,2], top_k_idx [N,2] (as float), auxiliary_loss scalar
//
// R6 (best kernel, 67.6us) with occupancy raised at fixed RPW=4:
//   - ring NSTG 5 -> 4 (32 KB static smem)
//   - __launch_bounds__(128, 6) forces <=85 regs -> 6 CTAs/SM = 24 warps/SM
// Everything else (weight layout, compute, reduction, epilogue) is unchanged.

#define D        2048
#define D4       512        // D / 4
#define NEXP     8
#define RPW      4          // rows per warp
#define WPB      4          // warps per block (128 threads)
#define RPB      (RPW*WPB)  // rows per block = 16
#define NSTG     4          // smem ring slots (3 stages in flight)

__device__ float    g_load[NEXP];
__device__ float    g_imp[NEXP];
__device__ unsigned g_ctr;
// Rearranged W_gate: [(i*4+j)*2 + half][lane] 16B units; half 0 = experts 0..3,
// half 1 = experts 4..7, for column c = i*128 + lane*4 + j.
__device__ float4   g_Wre[16 * 4 * 2 * 32];   // 64 KB

__device__ __forceinline__ unsigned long long pack2(float x, float y) {
    unsigned long long r;
    asm("mov.b64 %0, {%1, %2};" : "=l"(r) : "f"(x), "f"(y));
    return r;
}
__device__ __forceinline__ void unpack2(unsigned long long v, float& x, float& y) {
    asm("mov.b64 {%0, %1}, %2;" : "=f"(x), "=f"(y) : "l"(v));
}
__device__ __forceinline__ void ffma2(unsigned long long& d,
                                      unsigned long long a, unsigned long long b) {
    asm("fma.rn.f32x2 %0, %1, %2, %0;" : "+l"(d) : "l"(a), "l"(b));
}
__device__ __forceinline__ unsigned long long add2(unsigned long long a,
                                                   unsigned long long b) {
    unsigned long long r;
    asm("add.rn.f32x2 %0, %1, %2;" : "=l"(r) : "l"(a), "l"(b));
    return r;
}
__device__ __forceinline__ void cp16(void* smem_dst, const void* gsrc) {
    unsigned s = (unsigned)__cvta_generic_to_shared(smem_dst);
    asm volatile("cp.async.cg.shared.global [%0], [%1], 16;"
                 :: "r"(s), "l"(gsrc) : "memory");
}
#define CP_COMMIT()  asm volatile("cp.async.commit_group;" ::: "memory")
#define CP_WAIT2()   asm volatile("cp.async.wait_group 2;" ::: "memory")

// Rearrange W_gate into loop-order layout + zero the global accumulators.
__global__ void prep_kernel(const float* __restrict__ Wg) {
    const int c = blockIdx.x * 128 + threadIdx.x;           // column 0..2047
    const float4* Wg4 = (const float4*)Wg;
    float4 f0 = Wg4[c * 2];                                  // experts 0..3
    float4 f1 = Wg4[c * 2 + 1];                              // experts 4..7
    const int i = c >> 7, r = c & 127, lane = r >> 2, j = r & 3;
    const int base = ((i * 4 + j) * 2) * 32 + lane;
    g_Wre[base]      = f0;
    g_Wre[base + 32] = f1;
    if (blockIdx.x == 0) {
        if (threadIdx.x < NEXP) { g_load[threadIdx.x] = 0.f; g_imp[threadIdx.x] = 0.f; }
        if (threadIdx.x == NEXP) g_ctr = 0u;
    }
}

__global__ __launch_bounds__(128, 6)
void router_main(const float* __restrict__ x,
                 float* __restrict__ out_w, float* __restrict__ out_idx,
                 float* __restrict__ out_aux) {
    // Per-warp private x staging ring: [warp][slot][row][lane] 16B units = 32KB.
    __shared__ float4 s_x[WPB][NSTG][RPW][32];
    __shared__ float s_load[NEXP];
    __shared__ float s_imp[NEXP];
    __shared__ unsigned s_ticket;
    const int tid  = threadIdx.x;
    const int warp = tid >> 5;
    const int lane = tid & 31;

    if (tid < NEXP) { s_load[tid] = 0.f; s_imp[tid] = 0.f; }
    __syncthreads();

    const int r0 = (blockIdx.x * WPB + warp) * RPW;          // first row for this warp

    const float4*     x4 = (const float4*)x;
    const ulonglong2* wq = (const ulonglong2*)g_Wre;         // 16B units, dense per warp
    const float4*     gsrc = x4 + (size_t)r0 * D4 + lane;

    unsigned long long acc[RPW][4];
#pragma unroll
    for (int rr = 0; rr < RPW; rr++)
#pragma unroll
        for (int p = 0; p < 4; p++) acc[rr][p] = 0ull;

    // Prologue: issue 3 stages (lane-private 16B copies — no barriers needed).
#pragma unroll
    for (int st = 0; st < 3; st++) {
#pragma unroll
        for (int rr = 0; rr < RPW; rr++)
            cp16(&s_x[warp][st][rr][lane], gsrc + rr * D4 + st * 32);
        CP_COMMIT();
    }

#pragma unroll 1
    for (int i = 0; i < 16; i++) {                           // 16 groups of 128 cols
        CP_WAIT2();                                          // stage i landed
        __syncwarp();

        const int sl = i % NSTG;
        float4 xv[RPW];
#pragma unroll
        for (int rr = 0; rr < RPW; rr++)
            xv[rr] = s_x[warp][sl][rr][lane];                // LDS.128, lane-private

        // Refill: issue stage i+3 into the slot consumed at iter i-1.
        if (i + 3 < 16) {
            const int st = i + 3, sl2 = st % NSTG;
#pragma unroll
            for (int rr = 0; rr < RPW; rr++)
                cp16(&s_x[warp][sl2][rr][lane], gsrc + rr * D4 + st * 32);
        }
        CP_COMMIT();                                         // commit (possibly empty)

#pragma unroll
        for (int j = 0; j < 4; j++) {
            // Dense, L1-resident weight loads (lane stride = 16B)
            ulonglong2 wa = wq[((i * 4 + j) * 2 + 0) * 32 + lane];  // experts 0..3
            ulonglong2 wb = wq[((i * 4 + j) * 2 + 1) * 32 + lane];  // experts 4..7
#pragma unroll
            for (int rr = 0; rr < RPW; rr++) {
                float xc = (j == 0) ? xv[rr].x : (j == 1) ? xv[rr].y
                         : (j == 2) ? xv[rr].z : xv[rr].w;
                unsigned long long xb = pack2(xc, xc);
                ffma2(acc[rr][0], xb, wa.x);
                ffma2(acc[rr][1], xb, wa.y);
                ffma2(acc[rr][2], xb, wb.x);
                ffma2(acc[rr][3], xb, wb.y);
            }
        }
    }

    // Cross-lane reduction: 64-bit butterfly (once per 4 rows).
#pragma unroll
    for (int rr = 0; rr < RPW; rr++)
#pragma unroll
        for (int p = 0; p < 4; p++) {
#pragma unroll
            for (int off = 16; off > 0; off >>= 1)
                acc[rr][p] = add2(acc[rr][p],
                                  __shfl_xor_sync(0xffffffffu, acc[rr][p], off));
        }

    // Lane rr owns row r0+rr for the epilogue.
    unsigned long long mine[4];
#pragma unroll
    for (int rr = 0; rr < RPW; rr++)
        if (lane == rr) {
            mine[0] = acc[rr][0]; mine[1] = acc[rr][1];
            mine[2] = acc[rr][2]; mine[3] = acc[rr][3];
        }

    if (lane < RPW) {
        float h[NEXP];
        unpack2(mine[0], h[0], h[1]);
        unpack2(mine[1], h[2], h[3]);
        unpack2(mine[2], h[4], h[5]);
        unpack2(mine[3], h[6], h[7]);

        const int row = r0 + lane;

        // top-2 (lowest index wins ties, matching jax.lax.top_k)
        int e0 = 0; float v0 = h[0];
#pragma unroll
        for (int e = 1; e < NEXP; e++)
            if (h[e] > v0) { v0 = h[e]; e0 = e; }
        int e1 = -1; float v1 = -3.4e38f;
#pragma unroll
        for (int e = 0; e < NEXP; e++)
            if (e != e0 && h[e] > v1) { v1 = h[e]; e1 = e; }

        float w0 = 1.f / (1.f + expf(v1 - v0));
        float w1 = 1.f - w0;

        float p[NEXP]; float Z = 0.f;
#pragma unroll
        for (int e = 0; e < NEXP; e++) { p[e] = expf(h[e] - v0); Z += p[e]; }
        float invZ = 1.f / Z;
#pragma unroll
        for (int e = 0; e < NEXP; e++) atomicAdd(&s_imp[e], p[e] * invZ);
        atomicAdd(&s_load[e0], 1.f);
        atomicAdd(&s_load[e1], 1.f);

        out_w[row * 2]       = w0;
        out_w[row * 2 + 1]   = w1;
        out_idx[row * 2]     = (float)e0;
        out_idx[row * 2 + 1] = (float)e1;
    }

    __syncthreads();
    if (tid < NEXP) {
        atomicAdd(&g_load[tid], s_load[tid]);
        atomicAdd(&g_imp[tid],  s_imp[tid]);
        __threadfence();
    }
    __syncthreads();
    if (tid == 0) s_ticket = atomicAdd(&g_ctr, 1u);
    __syncthreads();

    // Last block computes the auxiliary loss.
    if (s_ticket == gridDim.x - 1 && tid == 0) {
        volatile float* vl_ = g_load;
        volatile float* vi_ = g_imp;
        float l[NEXP], im[NEXP];
        float ml = 0.f, mi = 0.f;
#pragma unroll
        for (int e = 0; e < NEXP; e++) {
            l[e] = vl_[e]; im[e] = vi_[e];
            ml += l[e];    mi += im[e];
        }
        ml *= (1.f / NEXP);
        mi *= (1.f / NEXP);
        float vl = 0.f, vi = 0.f;
#pragma unroll
        for (int e = 0; e < NEXP; e++) {
            float dl = l[e]  - ml; vl += dl * dl;
            float di = im[e] - mi; vi += di * di;
        }
        vl *= (1.f / (NEXP - 1));   // ddof = 1
        vi *= (1.f / (NEXP - 1));
        float cv = sqrtf(vl) / (ml + 1e-6f) + sqrtf(vi) / (mi + 1e-6f);
        *out_aux = cv * 0.01f;
    }
}

extern "C" void kernel_launch(void* const* d_in, const int* in_sizes, int n_in,
                              void* d_out, int out_size) {
    const float* x  = (const float*)d_in[0];   // [4,8192,2048]
    const float* Wg = (const float*)d_in[1];   // [2048,8]
    // d_in[2] = W_noise (unused in eval), d_in[3] = top_k (=2)

    const int N = in_sizes[0] / D;             // 32768 rows

    float* out     = (float*)d_out;
    float* out_w   = out;                      // [N,2]
    float* out_idx = out + (size_t)N * 2;      // [N,2]
    float* out_aux = out + (size_t)N * 4;      // scalar

    prep_kernel<<<16, 128>>>(Wg);
    router_main<<<N / RPB, 128>>>(x, out_w, out_idx, out_aux);
}

// round 16
// speedup vs baseline: 2.4684x; 1.2413x over previous
#include <cuda_runtime.h>
#include <math.h>

// NoisyTopKRouter eval-mode:
//   inputs:  x [4,8192,2048] f32, W_gate [2048,8] f32, W_noise (UNUSED), top_k=2
//   outputs (f32, concatenated in d_out):
//     dispatch_weights [N,2], top_k_idx [N,2] (as float), auxiliary_loss scalar
//
// R6 (best kernel, 67.6us) with two zero-risk trims:
//   1. __syncwarp removed: each lane reads back exactly the 16B it cp.async'd
//      itself (lane-private slots; wait_group is per-thread) -> sync redundant.
//   2. cp.async carries .L2::256B prefetch hint: the next 128-col stage
//      continues in the same rows, so the over-fetch is always consumed.
// Everything else (ring depth, weight layout, compute, reduction, epilogue)
// is byte-identical to the proven 67.6us kernel.

#define D        2048
#define D4       512        // D / 4
#define NEXP     8
#define RPW      4          // rows per warp
#define WPB      4          // warps per block (128 threads)
#define RPB      (RPW*WPB)  // rows per block = 16
#define NSTG     5          // smem ring slots (4 stages in flight)

__device__ float    g_load[NEXP];
__device__ float    g_imp[NEXP];
__device__ unsigned g_ctr;
// Rearranged W_gate: [(i*4+j)*2 + half][lane] 16B units; half 0 = experts 0..3,
// half 1 = experts 4..7, for column c = i*128 + lane*4 + j.
__device__ float4   g_Wre[16 * 4 * 2 * 32];   // 64 KB

__device__ __forceinline__ unsigned long long pack2(float x, float y) {
    unsigned long long r;
    asm("mov.b64 %0, {%1, %2};" : "=l"(r) : "f"(x), "f"(y));
    return r;
}
__device__ __forceinline__ void unpack2(unsigned long long v, float& x, float& y) {
    asm("mov.b64 {%0, %1}, %2;" : "=f"(x), "=f"(y) : "l"(v));
}
__device__ __forceinline__ void ffma2(unsigned long long& d,
                                      unsigned long long a, unsigned long long b) {
    asm("fma.rn.f32x2 %0, %1, %2, %0;" : "+l"(d) : "l"(a), "l"(b));
}
__device__ __forceinline__ unsigned long long add2(unsigned long long a,
                                                   unsigned long long b) {
    unsigned long long r;
    asm("add.rn.f32x2 %0, %1, %2;" : "=l"(r) : "l"(a), "l"(b));
    return r;
}
__device__ __forceinline__ void cp16(void* smem_dst, const void* gsrc) {
    unsigned s = (unsigned)__cvta_generic_to_shared(smem_dst);
    asm volatile("cp.async.cg.shared.global.L2::256B [%0], [%1], 16;"
                 :: "r"(s), "l"(gsrc) : "memory");
}
#define CP_COMMIT()  asm volatile("cp.async.commit_group;" ::: "memory")
#define CP_WAIT(n)   asm volatile("cp.async.wait_group %0;" :: "n"(n) : "memory")

// Rearrange W_gate into loop-order layout + zero the global accumulators.
__global__ void prep_kernel(const float* __restrict__ Wg) {
    const int c = blockIdx.x * 128 + threadIdx.x;           // column 0..2047
    const float4* Wg4 = (const float4*)Wg;
    float4 f0 = Wg4[c * 2];                                  // experts 0..3
    float4 f1 = Wg4[c * 2 + 1];                              // experts 4..7
    const int i = c >> 7, r = c & 127, lane = r >> 2, j = r & 3;
    const int base = ((i * 4 + j) * 2) * 32 + lane;
    g_Wre[base]      = f0;
    g_Wre[base + 32] = f1;
    if (blockIdx.x == 0) {
        if (threadIdx.x < NEXP) { g_load[threadIdx.x] = 0.f; g_imp[threadIdx.x] = 0.f; }
        if (threadIdx.x == NEXP) g_ctr = 0u;
    }
}

__global__ __launch_bounds__(128, 4)
void router_main(const float* __restrict__ x,
                 float* __restrict__ out_w, float* __restrict__ out_idx,
                 float* __restrict__ out_aux) {
    // Per-warp private x staging ring: [warp][slot][row][lane] 16B units = 40KB.
    __shared__ float4 s_x[WPB][NSTG][RPW][32];
    __shared__ float s_load[NEXP];
    __shared__ float s_imp[NEXP];
    __shared__ unsigned s_ticket;
    const int tid  = threadIdx.x;
    const int warp = tid >> 5;
    const int lane = tid & 31;

    if (tid < NEXP) { s_load[tid] = 0.f; s_imp[tid] = 0.f; }
    __syncthreads();

    const int r0 = (blockIdx.x * WPB + warp) * RPW;          // first row for this warp

    const float4*     x4 = (const float4*)x;
    const ulonglong2* wq = (const ulonglong2*)g_Wre;         // 16B units, dense per warp
    const float4*     gsrc = x4 + (size_t)r0 * D4 + lane;

    unsigned long long acc[RPW][4];
#pragma unroll
    for (int rr = 0; rr < RPW; rr++)
#pragma unroll
        for (int p = 0; p < 4; p++) acc[rr][p] = 0ull;

    // Prologue: issue 4 stages (lane-private 16B copies — no barriers needed).
#pragma unroll
    for (int st = 0; st < 4; st++) {
#pragma unroll
        for (int rr = 0; rr < RPW; rr++)
            cp16(&s_x[warp][st][rr][lane], gsrc + rr * D4 + st * 32);
        CP_COMMIT();
    }

#pragma unroll 1
    for (int i = 0; i < 16; i++) {                           // 16 groups of 128 cols
        CP_WAIT(3);                                          // stage i landed
        // (no __syncwarp needed: each lane reads only the bytes it copied)

        const int sl = i % NSTG;
        float4 xv[RPW];
#pragma unroll
        for (int rr = 0; rr < RPW; rr++)
            xv[rr] = s_x[warp][sl][rr][lane];                // LDS.128, lane-private

        // Refill: issue stage i+4 into the slot consumed at iter i-1.
        if (i + 4 < 16) {
            const int st = i + 4, sl2 = st % NSTG;
#pragma unroll
            for (int rr = 0; rr < RPW; rr++)
                cp16(&s_x[warp][sl2][rr][lane], gsrc + rr * D4 + st * 32);
        }
        CP_COMMIT();                                         // commit (possibly empty)

#pragma unroll
        for (int j = 0; j < 4; j++) {
            // Dense, L1-resident weight loads (lane stride = 16B)
            ulonglong2 wa = wq[((i * 4 + j) * 2 + 0) * 32 + lane];  // experts 0..3
            ulonglong2 wb = wq[((i * 4 + j) * 2 + 1) * 32 + lane];  // experts 4..7
#pragma unroll
            for (int rr = 0; rr < RPW; rr++) {
                float xc = (j == 0) ? xv[rr].x : (j == 1) ? xv[rr].y
                         : (j == 2) ? xv[rr].z : xv[rr].w;
                unsigned long long xb = pack2(xc, xc);
                ffma2(acc[rr][0], xb, wa.x);
                ffma2(acc[rr][1], xb, wa.y);
                ffma2(acc[rr][2], xb, wb.x);
                ffma2(acc[rr][3], xb, wb.y);
            }
        }
    }

    // Cross-lane reduction: 64-bit butterfly (once per 4 rows).
#pragma unroll
    for (int rr = 0; rr < RPW; rr++)
#pragma unroll
        for (int p = 0; p < 4; p++) {
#pragma unroll
            for (int off = 16; off > 0; off >>= 1)
                acc[rr][p] = add2(acc[rr][p],
                                  __shfl_xor_sync(0xffffffffu, acc[rr][p], off));
        }

    // Lane rr owns row r0+rr for the epilogue.
    unsigned long long mine[4];
#pragma unroll
    for (int rr = 0; rr < RPW; rr++)
        if (lane == rr) {
            mine[0] = acc[rr][0]; mine[1] = acc[rr][1];
            mine[2] = acc[rr][2]; mine[3] = acc[rr][3];
        }

    if (lane < RPW) {
        float h[NEXP];
        unpack2(mine[0], h[0], h[1]);
        unpack2(mine[1], h[2], h[3]);
        unpack2(mine[2], h[4], h[5]);
        unpack2(mine[3], h[6], h[7]);

        const int row = r0 + lane;

        // top-2 (lowest index wins ties, matching jax.lax.top_k)
        int e0 = 0; float v0 = h[0];
#pragma unroll
        for (int e = 1; e < NEXP; e++)
            if (h[e] > v0) { v0 = h[e]; e0 = e; }
        int e1 = -1; float v1 = -3.4e38f;
#pragma unroll
        for (int e = 0; e < NEXP; e++)
            if (e != e0 && h[e] > v1) { v1 = h[e]; e1 = e; }

        float w0 = 1.f / (1.f + expf(v1 - v0));
        float w1 = 1.f - w0;

        float p[NEXP]; float Z = 0.f;
#pragma unroll
        for (int e = 0; e < NEXP; e++) { p[e] = expf(h[e] - v0); Z += p[e]; }
        float invZ = 1.f / Z;
#pragma unroll
        for (int e = 0; e < NEXP; e++) atomicAdd(&s_imp[e], p[e] * invZ);
        atomicAdd(&s_load[e0], 1.f);
        atomicAdd(&s_load[e1], 1.f);

        out_w[row * 2]       = w0;
        out_w[row * 2 + 1]   = w1;
        out_idx[row * 2]     = (float)e0;
        out_idx[row * 2 + 1] = (float)e1;
    }

    __syncthreads();
    if (tid < NEXP) {
        atomicAdd(&g_load[tid], s_load[tid]);
        atomicAdd(&g_imp[tid],  s_imp[tid]);
        __threadfence();
    }
    __syncthreads();
    if (tid == 0) s_ticket = atomicAdd(&g_ctr, 1u);
    __syncthreads();

    // Last block computes the auxiliary loss.
    if (s_ticket == gridDim.x - 1 && tid == 0) {
        volatile float* vl_ = g_load;
        volatile float* vi_ = g_imp;
        float l[NEXP], im[NEXP];
        float ml = 0.f, mi = 0.f;
#pragma unroll
        for (int e = 0; e < NEXP; e++) {
            l[e] = vl_[e]; im[e] = vi_[e];
            ml += l[e];    mi += im[e];
        }
        ml *= (1.f / NEXP);
        mi *= (1.f / NEXP);
        float vl = 0.f, vi = 0.f;
#pragma unroll
        for (int e = 0; e < NEXP; e++) {
            float dl = l[e]  - ml; vl += dl * dl;
            float di = im[e] - mi; vi += di * di;
        }
        vl *= (1.f / (NEXP - 1));   // ddof = 1
        vi *= (1.f / (NEXP - 1));
        float cv = sqrtf(vl) / (ml + 1e-6f) + sqrtf(vi) / (mi + 1e-6f);
        *out_aux = cv * 0.01f;
    }
}

extern "C" void kernel_launch(void* const* d_in, const int* in_sizes, int n_in,
                              void* d_out, int out_size) {
    const float* x  = (const float*)d_in[0];   // [4,8192,2048]
    const float* Wg = (const float*)d_in[1];   // [2048,8]
    // d_in[2] = W_noise (unused in eval), d_in[3] = top_k (=2)

    const int N = in_sizes[0] / D;             // 32768 rows

    float* out     = (float*)d_out;
    float* out_w   = out;                      // [N,2]
    float* out_idx = out + (size_t)N * 2;      // [N,2]
    float* out_aux = out + (size_t)N * 4;      // scalar

    prep_kernel<<<16, 128>>>(Wg);
    router_main<<<N / RPB, 128>>>(x, out_w, out_idx, out_aux);
}